// round 5
// baseline (speedup 1.0000x reference)
#include <cuda_runtime.h>
#include <cstdint>

// Kohonen SOM pairwise L2 distance, persistent-CTA tf32 MMA pipeline.
//   out[b][n] = sqrt(max(x2[b] + w2[n] - 2 x_b.w_n, 0))
// x [65536,32] f32, w [4900,32] f32, out [B,N] f32.
//
// Kernel 1: precompute row norms x2, w2 into __device__ scratch.
// Kernel 2: persistent CTAs; tiles (128x128) ordered m-major within each
// n-column so Bs (w tile) is loaded ~once per CTA; As (x tile) double-
// buffered via cp.async.cg so fill latency hides behind the previous tile's
// MMA+epilogue. Operands raw fp32 into mma.sync.m16n8k8.tf32 (hw truncation).

#define BM 128
#define BN 128
#define KD 32
#define M_TILES 512            // 65536 / 128
#define TILE_SHIFT 9           // m_tile = t & 511, n_tile = t >> 9

// swizzled [128][32] float tile, pitch 32 (no padding):
// float index = row*32 + (col ^ (4*(row&7)))  -> fragment reads conflict-free
#define SIDX(row, col) (((row) << 5) + (((col) ^ (((row) & 7) << 2)) & 31))

#define TILE_FLOATS (BM * KD)      // 4096 floats = 16 KB
#define SMEM_BYTES  (3 * TILE_FLOATS * 4)   // As[2] + Bs = 48 KB exactly

__device__ float g_x2[65536];
__device__ float g_w2[8192];

__device__ __forceinline__ float fsqrt_approx(float a) {
    float r;
    asm("sqrt.approx.f32 %0, %1;" : "=f"(r) : "f"(a));
    return r;
}

__device__ __forceinline__ unsigned smem_u32(const void* p) {
    unsigned a;
    asm("{ .reg .u64 t; cvta.to.shared.u64 t, %1; cvt.u32.u64 %0, t; }"
        : "=r"(a) : "l"(p));
    return a;
}

__device__ __forceinline__ void cp16(unsigned saddr, const void* gaddr) {
    asm volatile("cp.async.cg.shared.global [%0], [%1], 16;"
                 :: "r"(saddr), "l"(gaddr));
}
__device__ __forceinline__ void cp16_pred(unsigned saddr, const void* gaddr, int src_sz) {
    asm volatile("cp.async.cg.shared.global [%0], [%1], 16, %2;"
                 :: "r"(saddr), "l"(gaddr), "r"(src_sz));
}
__device__ __forceinline__ void cp_commit() {
    asm volatile("cp.async.commit_group;");
}
__device__ __forceinline__ void cp_wait_all() {
    asm volatile("cp.async.wait_group 0;");
}

__device__ __forceinline__ void mma_tf32(float* c, const unsigned* a, const unsigned* b) {
    asm volatile(
        "mma.sync.aligned.m16n8k8.row.col.f32.tf32.tf32.f32 "
        "{%0,%1,%2,%3}, {%4,%5,%6,%7}, {%8,%9}, {%0,%1,%2,%3};"
        : "+f"(c[0]), "+f"(c[1]), "+f"(c[2]), "+f"(c[3])
        : "r"(a[0]), "r"(a[1]), "r"(a[2]), "r"(a[3]),
          "r"(b[0]), "r"(b[1]));
}

// ---- kernel 1: row norms ----
__global__ void norms_kernel(const float* __restrict__ x,
                             const float* __restrict__ w,
                             int B, int N) {
    int i = blockIdx.x * 256 + threadIdx.x;
    if (i < B) {
        const float4* s = (const float4*)(x + (size_t)i * KD);
        float n = 0.f;
        #pragma unroll
        for (int q = 0; q < 8; ++q) {
            float4 v = s[q];
            n = fmaf(v.x, v.x, n); n = fmaf(v.y, v.y, n);
            n = fmaf(v.z, v.z, n); n = fmaf(v.w, v.w, n);
        }
        g_x2[i] = n;
    }
    if (i < N) {
        const float4* s = (const float4*)(w + (size_t)i * KD);
        float n = 0.f;
        #pragma unroll
        for (int q = 0; q < 8; ++q) {
            float4 v = s[q];
            n = fmaf(v.x, v.x, n); n = fmaf(v.y, v.y, n);
            n = fmaf(v.z, v.z, n); n = fmaf(v.w, v.w, n);
        }
        g_w2[i] = n;
    }
}

// issue 4 cp.async per thread covering one 128x32 f32 tile
__device__ __forceinline__ void prefetch_x_tile(unsigned s_base, const float* x,
                                                int m_tile, int tid) {
    const float* src = x + (size_t)m_tile * BM * KD;
    #pragma unroll
    for (int p = 0; p < 4; ++p) {
        int idx = tid + p * 256;
        int row = idx >> 3;
        int q4  = (idx & 7) << 2;            // col base
        cp16(s_base + SIDX(row, q4) * 4, src + row * KD + q4);
    }
}

__device__ __forceinline__ void load_w_tile(unsigned s_base, const float* w,
                                            int n_tile, int N, int tid) {
    #pragma unroll
    for (int p = 0; p < 4; ++p) {
        int idx = tid + p * 256;
        int row = idx >> 3;
        int q4  = (idx & 7) << 2;
        int gn  = n_tile * BN + row;
        int sz  = (gn < N) ? 16 : 0;         // src_size 0 -> zero-fill, no read
        cp16_pred(s_base + SIDX(row, q4) * 4, w + (size_t)gn * KD + q4, sz);
    }
}

// ---- kernel 2: persistent tiles ----
__global__ __launch_bounds__(256, 2)
void som_mma_kernel(const float* __restrict__ x,
                    const float* __restrict__ w,
                    float* __restrict__ out,
                    int B, int N, int T, int chunk) {
    extern __shared__ float smem[];
    float* Asb[2] = { smem, smem + TILE_FLOATS };
    float* Bs     = smem + 2 * TILE_FLOATS;
    const unsigned as_u32[2] = { smem_u32(Asb[0]), smem_u32(Asb[1]) };
    const unsigned bs_u32    = smem_u32(Bs);

    const int tid  = threadIdx.x;
    const int lane = tid & 31;
    const int wid  = tid >> 5;
    const int warp_m = (wid & 3) * 32;       // 4 warps along M
    const int warp_n = (wid >> 2) * 64;      // 2 warps along N
    const int qr = lane >> 2;                // 0..7
    const int qc = lane & 3;                 // 0..3

    int start = blockIdx.x * chunk;
    int end   = min(start + chunk, T);
    if (start >= end) return;

    int cur = 0;
    int cur_n = -1;

    prefetch_x_tile(as_u32[0], x, start & (M_TILES - 1), tid);
    cp_commit();

    for (int t = start; t < end; ++t) {
        const int n_tile = t >> TILE_SHIFT;
        const int m_tile = t & (M_TILES - 1);

        if (n_tile != cur_n) {
            if (t != start) __syncthreads();     // everyone done reading old Bs
            load_w_tile(bs_u32, w, n_tile, N, tid);
            cp_commit();
            cur_n = n_tile;
        }

        cp_wait_all();
        __syncthreads();                         // As[cur] + Bs visible

        if (t + 1 < end) {
            prefetch_x_tile(as_u32[cur ^ 1], x, (t + 1) & (M_TILES - 1), tid);
            cp_commit();
        }

        const float* As = Asb[cur];

        // ---- mainloop ----
        float acc[2][8][4];
        #pragma unroll
        for (int i = 0; i < 2; ++i)
            #pragma unroll
            for (int j = 0; j < 8; ++j)
                #pragma unroll
                for (int v = 0; v < 4; ++v) acc[i][j][v] = 0.f;

        #pragma unroll
        for (int ks = 0; ks < 4; ++ks) {
            const int k0 = ks * 8;

            unsigned af[2][4];
            #pragma unroll
            for (int tm = 0; tm < 2; ++tm) {
                const int r = warp_m + tm * 16 + qr;
                af[tm][0] = __float_as_uint(As[SIDX(r,     k0 + qc    )]);
                af[tm][1] = __float_as_uint(As[SIDX(r + 8, k0 + qc    )]);
                af[tm][2] = __float_as_uint(As[SIDX(r,     k0 + qc + 4)]);
                af[tm][3] = __float_as_uint(As[SIDX(r + 8, k0 + qc + 4)]);
            }

            unsigned bf[8][2];
            #pragma unroll
            for (int tn = 0; tn < 8; ++tn) {
                const int c = warp_n + tn * 8 + qr;
                bf[tn][0] = __float_as_uint(Bs[SIDX(c, k0 + qc    )]);
                bf[tn][1] = __float_as_uint(Bs[SIDX(c, k0 + qc + 4)]);
            }

            #pragma unroll
            for (int tm = 0; tm < 2; ++tm)
                #pragma unroll
                for (int tn = 0; tn < 8; ++tn)
                    mma_tf32(acc[tm][tn], af[tm], bf[tn]);
        }

        // ---- epilogue ----
        const int m_base = m_tile * BM;
        const int n_base = n_tile * BN;
        const int qc2 = qc * 2;

        #pragma unroll
        for (int tm = 0; tm < 2; ++tm) {
            const int r_lo = warp_m + tm * 16 + qr;
            const float x2_lo = g_x2[m_base + r_lo];
            const float x2_hi = g_x2[m_base + r_lo + 8];
            const size_t off_lo = (size_t)(m_base + r_lo) * N;
            const size_t off_hi = off_lo + (size_t)8 * N;

            #pragma unroll
            for (int tn = 0; tn < 8; ++tn) {
                const int c  = warp_n + tn * 8 + qc2;
                const int gn = n_base + c;
                if (gn < N) {                    // N even, c even -> gn+1 valid
                    const float w2a = g_w2[gn];
                    const float w2b = g_w2[gn + 1];
                    const float* a  = acc[tm][tn];

                    float2 lo, hi;
                    lo.x = fsqrt_approx(fmaxf(fmaf(-2.f, a[0], x2_lo + w2a), 0.f));
                    lo.y = fsqrt_approx(fmaxf(fmaf(-2.f, a[1], x2_lo + w2b), 0.f));
                    hi.x = fsqrt_approx(fmaxf(fmaf(-2.f, a[2], x2_hi + w2a), 0.f));
                    hi.y = fsqrt_approx(fmaxf(fmaf(-2.f, a[3], x2_hi + w2b), 0.f));

                    __stcs((float2*)(out + off_lo + gn), lo);
                    __stcs((float2*)(out + off_hi + gn), hi);
                }
            }
        }

        cur ^= 1;
    }
}

extern "C" void kernel_launch(void* const* d_in, const int* in_sizes, int n_in,
                              void* d_out, int out_size) {
    const float* x = (const float*)d_in[0];
    const float* w = (const float*)d_in[1];
    float* out     = (float*)d_out;

    int B = in_sizes[0] / KD;   // 65536
    int N = in_sizes[1] / KD;   // 4900

    norms_kernel<<<(B + 255) / 256, 256>>>(x, w, B, N);

    int n_tiles = (N + BN - 1) / BN;         // 39
    int T = n_tiles * M_TILES;               // 19968

    int sms = 148;
    cudaDeviceGetAttribute(&sms, cudaDevAttrMultiProcessorCount, 0);
    int grid = sms * 2;
    int chunk = (T + grid - 1) / grid;

    som_mma_kernel<<<grid, 256, SMEM_BYTES>>>(x, w, out, B, N, T, chunk);
}

// round 6
// speedup vs baseline: 1.1661x; 1.1661x over previous
#include <cuda_runtime.h>
#include <cstdint>

// Kohonen SOM pairwise L2 distance via tf32 mma.sync.m16n8k8.
//   out[b][n] = sqrt(max(||x_b||^2 + ||w_n||^2 - 2 x_b.w_n, 0))
// x [B=65536,32] f32, w [N=4900,32] f32, out [B,N] f32.
//
// R6: occupancy-targeted. CTA tile 128x64, 256 threads, 8 warps in a 4x2
// grid, 32x32 warp tile (acc = 32 regs/thread). __launch_bounds__(256,3)
// -> 3 CTAs/SM (24 warps, 37.5% occ) vs the 2-CTA/24% of the 128x128
// version. One-shot CTAs (persistence regressed in R5); grid is n-major so
// each wave shares the full w matrix in L2.

#define BM 128
#define BN 64
#define KD 32

// swizzled [rows][32] float tile, pitch 32: idx = row*32 + (col ^ (4*(row&7)))
// -> all m16n8k8 fragment reads and float4 fills are bank-conflict-free
#define SIDX(row, col) (((row) << 5) + (((col) ^ (((row) & 7) << 2)) & 31))

__device__ __forceinline__ float to_tf32(float a) {
    float r;
    asm("cvt.rna.tf32.f32 %0, %1;" : "=f"(r) : "f"(a));
    return r;
}

__device__ __forceinline__ float fsqrt_approx(float a) {
    float r;
    asm("sqrt.approx.f32 %0, %1;" : "=f"(r) : "f"(a));
    return r;
}

__device__ __forceinline__ void mma_tf32(float* c, const unsigned* a, const unsigned* b) {
    asm volatile(
        "mma.sync.aligned.m16n8k8.row.col.f32.tf32.tf32.f32 "
        "{%0,%1,%2,%3}, {%4,%5,%6,%7}, {%8,%9}, {%0,%1,%2,%3};"
        : "+f"(c[0]), "+f"(c[1]), "+f"(c[2]), "+f"(c[3])
        : "r"(a[0]), "r"(a[1]), "r"(a[2]), "r"(a[3]),
          "r"(b[0]), "r"(b[1]));
}

__global__ __launch_bounds__(256, 3)
void som_mma_kernel(const float* __restrict__ x,
                    const float* __restrict__ w,
                    float* __restrict__ out,
                    int B, int N) {
    __shared__ float As[BM * KD];     // 16 KB, swizzled
    __shared__ float Bs[BN * KD];     // 8 KB, swizzled
    __shared__ float x2s[BM];
    __shared__ float w2s[BN];

    const int tid    = threadIdx.x;
    const int m_base = blockIdx.y * BM;
    const int n_base = blockIdx.x * BN;

    // ---- fill: threads 0..127 -> x rows, 128..191 -> w rows ----
    if (tid < BM) {
        const float4* src = (const float4*)(x + (size_t)(m_base + tid) * KD);
        float nrm = 0.f;
        #pragma unroll
        for (int q = 0; q < 8; ++q) {
            float4 v = src[q];
            nrm = fmaf(v.x, v.x, nrm); nrm = fmaf(v.y, v.y, nrm);
            nrm = fmaf(v.z, v.z, nrm); nrm = fmaf(v.w, v.w, nrm);
            float4 t = make_float4(to_tf32(v.x), to_tf32(v.y),
                                   to_tf32(v.z), to_tf32(v.w));
            *(float4*)&As[SIDX(tid, q * 4)] = t;
        }
        x2s[tid] = nrm;
    } else if (tid < BM + BN) {
        const int row = tid - BM;
        const int gn  = n_base + row;
        float nrm = 0.f;
        if (gn < N) {
            const float4* src = (const float4*)(w + (size_t)gn * KD);
            #pragma unroll
            for (int q = 0; q < 8; ++q) {
                float4 v = src[q];
                nrm = fmaf(v.x, v.x, nrm); nrm = fmaf(v.y, v.y, nrm);
                nrm = fmaf(v.z, v.z, nrm); nrm = fmaf(v.w, v.w, nrm);
                float4 t = make_float4(to_tf32(v.x), to_tf32(v.y),
                                       to_tf32(v.z), to_tf32(v.w));
                *(float4*)&Bs[SIDX(row, q * 4)] = t;
            }
        } else {
            float4 z = make_float4(0.f, 0.f, 0.f, 0.f);
            #pragma unroll
            for (int q = 0; q < 8; ++q) *(float4*)&Bs[SIDX(row, q * 4)] = z;
        }
        w2s[row] = nrm;
    }
    __syncthreads();

    // ---- 32x32 warp tile: 2 m-frags x 4 n-frags per k-step ----
    const int lane   = tid & 31;
    const int wid    = tid >> 5;
    const int warp_m = (wid & 3) * 32;   // 4 warps along M
    const int warp_n = (wid >> 2) * 32;  // 2 warps along N
    const int qr     = lane >> 2;        // 0..7
    const int qc     = lane & 3;         // 0..3

    float acc[2][4][4];
    #pragma unroll
    for (int i = 0; i < 2; ++i)
        #pragma unroll
        for (int j = 0; j < 4; ++j)
            #pragma unroll
            for (int v = 0; v < 4; ++v) acc[i][j][v] = 0.f;

    #pragma unroll
    for (int ks = 0; ks < 4; ++ks) {
        const int k0 = ks * 8;

        unsigned af[2][4];
        #pragma unroll
        for (int tm = 0; tm < 2; ++tm) {
            const int r = warp_m + tm * 16 + qr;
            af[tm][0] = __float_as_uint(As[SIDX(r,     k0 + qc    )]);
            af[tm][1] = __float_as_uint(As[SIDX(r + 8, k0 + qc    )]);
            af[tm][2] = __float_as_uint(As[SIDX(r,     k0 + qc + 4)]);
            af[tm][3] = __float_as_uint(As[SIDX(r + 8, k0 + qc + 4)]);
        }

        unsigned bf[4][2];
        #pragma unroll
        for (int tn = 0; tn < 4; ++tn) {
            const int c = warp_n + tn * 8 + qr;
            bf[tn][0] = __float_as_uint(Bs[SIDX(c, k0 + qc    )]);
            bf[tn][1] = __float_as_uint(Bs[SIDX(c, k0 + qc + 4)]);
        }

        #pragma unroll
        for (int tm = 0; tm < 2; ++tm)
            #pragma unroll
            for (int tn = 0; tn < 4; ++tn)
                mma_tf32(acc[tm][tn], af[tm], bf[tn]);
    }

    // ---- epilogue: norms + sqrt, float2 stores ----
    const int qc2 = qc * 2;
    #pragma unroll
    for (int tm = 0; tm < 2; ++tm) {
        const int r_lo = warp_m + tm * 16 + qr;
        const float x2_lo = x2s[r_lo];
        const float x2_hi = x2s[r_lo + 8];
        const size_t off_lo = (size_t)(m_base + r_lo) * N;
        const size_t off_hi = off_lo + (size_t)8 * N;

        #pragma unroll
        for (int tn = 0; tn < 4; ++tn) {
            const int c  = warp_n + tn * 8 + qc2;
            const int gn = n_base + c;
            if (gn < N) {                 // N even, c even -> gn+1 valid too
                const float w2a = w2s[c];
                const float w2b = w2s[c + 1];
                const float* a  = acc[tm][tn];

                float2 lo, hi;
                lo.x = fsqrt_approx(fmaxf(fmaf(-2.f, a[0], x2_lo + w2a), 0.f));
                lo.y = fsqrt_approx(fmaxf(fmaf(-2.f, a[1], x2_lo + w2b), 0.f));
                hi.x = fsqrt_approx(fmaxf(fmaf(-2.f, a[2], x2_hi + w2a), 0.f));
                hi.y = fsqrt_approx(fmaxf(fmaf(-2.f, a[3], x2_hi + w2b), 0.f));

                __stcs((float2*)(out + off_lo + gn), lo);
                __stcs((float2*)(out + off_hi + gn), hi);
            }
        }
    }
}

extern "C" void kernel_launch(void* const* d_in, const int* in_sizes, int n_in,
                              void* d_out, int out_size) {
    const float* x = (const float*)d_in[0];
    const float* w = (const float*)d_in[1];
    float* out     = (float*)d_out;

    int B = in_sizes[0] / KD;   // 65536
    int N = in_sizes[1] / KD;   // 4900

    dim3 grid((N + BN - 1) / BN, (B + BM - 1) / BM);   // (77, 512), n-major waves
    som_mma_kernel<<<grid, 256>>>(x, w, out, B, N);
}

// round 7
// speedup vs baseline: 1.3639x; 1.1696x over previous
#include <cuda_runtime.h>
#include <cstdint>

// Kohonen SOM pairwise L2 distance via tf32 mma.sync.m16n8k8.
//   out[b][n] = sqrt(max(||x_b||^2 + ||w_n||^2 - 2 x_b.w_n, 0))
// x [B=65536,32] f32, w [N=4900,32] f32, out [B,N] f32.
//
// R7: R3 structure (128x128 tile, 256 threads, 4x2 warps, 32x64 warp tile)
// + fragment-column PERMUTATION: B-fragment column j of fragment tn sources
// physical w-column perm(tn,j) = (j>>1)*4 + (tn>>1)*16 + (tn&1)*2 + (j&1).
// Each thread then owns 4 consecutive output columns per fragment pair, so
// the epilogue is STG.128 (64B/wavefront) instead of STG.64 (32B/wavefront):
// store wavefronts and store instructions both halve. Smem swizzle updated
// to col ^ (4*((row^(row>>1))&7)) so the permuted fragment rows stay
// bank-conflict-free (old row&7 swizzle collides for rows {0,1,4,5,8,...}).

#define BM 128
#define BN 128
#define KD 32

#define SWZ(row) ((((row) ^ ((row) >> 1)) & 7) << 2)
#define SIDX(row, col) (((row) << 5) + (((col) ^ SWZ(row)) & 31))

__device__ __forceinline__ float to_tf32(float a) {
    float r;
    asm("cvt.rna.tf32.f32 %0, %1;" : "=f"(r) : "f"(a));
    return r;
}

__device__ __forceinline__ float fsqrt_approx(float a) {
    float r;
    asm("sqrt.approx.f32 %0, %1;" : "=f"(r) : "f"(a));
    return r;
}

__device__ __forceinline__ void mma_tf32(float* c, const unsigned* a, const unsigned* b) {
    asm volatile(
        "mma.sync.aligned.m16n8k8.row.col.f32.tf32.tf32.f32 "
        "{%0,%1,%2,%3}, {%4,%5,%6,%7}, {%8,%9}, {%0,%1,%2,%3};"
        : "+f"(c[0]), "+f"(c[1]), "+f"(c[2]), "+f"(c[3])
        : "r"(a[0]), "r"(a[1]), "r"(a[2]), "r"(a[3]),
          "r"(b[0]), "r"(b[1]));
}

__global__ __launch_bounds__(256, 2)
void som_mma_kernel(const float* __restrict__ x,
                    const float* __restrict__ w,
                    float* __restrict__ out,
                    int B, int N) {
    __shared__ float As[BM * KD];     // 16 KB, swizzled
    __shared__ float Bs[BN * KD];     // 16 KB, swizzled
    __shared__ float x2s[BM];
    __shared__ float w2s[BN];

    const int tid    = threadIdx.x;
    const int m_base = blockIdx.y * BM;
    const int n_base = blockIdx.x * BN;

    // ---- fill: threads 0..127 -> x rows, 128..255 -> w rows ----
    if (tid < BM) {
        const float4* src = (const float4*)(x + (size_t)(m_base + tid) * KD);
        float nrm = 0.f;
        #pragma unroll
        for (int q = 0; q < 8; ++q) {
            float4 v = src[q];
            nrm = fmaf(v.x, v.x, nrm); nrm = fmaf(v.y, v.y, nrm);
            nrm = fmaf(v.z, v.z, nrm); nrm = fmaf(v.w, v.w, nrm);
            float4 t = make_float4(to_tf32(v.x), to_tf32(v.y),
                                   to_tf32(v.z), to_tf32(v.w));
            *(float4*)&As[SIDX(tid, q * 4)] = t;
        }
        x2s[tid] = nrm;
    } else {
        const int row = tid - BM;
        const int gn  = n_base + row;
        float nrm = 0.f;
        if (gn < N) {
            const float4* src = (const float4*)(w + (size_t)gn * KD);
            #pragma unroll
            for (int q = 0; q < 8; ++q) {
                float4 v = src[q];
                nrm = fmaf(v.x, v.x, nrm); nrm = fmaf(v.y, v.y, nrm);
                nrm = fmaf(v.z, v.z, nrm); nrm = fmaf(v.w, v.w, nrm);
                float4 t = make_float4(to_tf32(v.x), to_tf32(v.y),
                                       to_tf32(v.z), to_tf32(v.w));
                *(float4*)&Bs[SIDX(row, q * 4)] = t;
            }
        } else {
            float4 z = make_float4(0.f, 0.f, 0.f, 0.f);
            #pragma unroll
            for (int q = 0; q < 8; ++q) *(float4*)&Bs[SIDX(row, q * 4)] = z;
        }
        w2s[row] = nrm;
    }
    __syncthreads();

    // ---- warp-tiled mainloop with permuted B-fragment columns ----
    const int lane   = tid & 31;
    const int wid    = tid >> 5;
    const int warp_m = (wid & 3) * 32;   // 4 warps along M
    const int warp_n = (wid >> 2) * 64;  // 2 warps along N
    const int qr     = lane >> 2;        // 0..7
    const int qc     = lane & 3;         // 0..3

    // physical w-row feeding fragment-col qr of fragment tn:
    //   warp_n + (qr>>1)*4 + (qr&1) + (tn>>1)*16 + (tn&1)*2
    const int pq = (qr >> 1) * 4 + (qr & 1);

    float acc[2][8][4];
    #pragma unroll
    for (int i = 0; i < 2; ++i)
        #pragma unroll
        for (int j = 0; j < 8; ++j)
            #pragma unroll
            for (int v = 0; v < 4; ++v) acc[i][j][v] = 0.f;

    #pragma unroll
    for (int ks = 0; ks < 4; ++ks) {
        const int k0 = ks * 8;

        unsigned af[2][4];
        #pragma unroll
        for (int tm = 0; tm < 2; ++tm) {
            const int r = warp_m + tm * 16 + qr;
            af[tm][0] = __float_as_uint(As[SIDX(r,     k0 + qc    )]);
            af[tm][1] = __float_as_uint(As[SIDX(r + 8, k0 + qc    )]);
            af[tm][2] = __float_as_uint(As[SIDX(r,     k0 + qc + 4)]);
            af[tm][3] = __float_as_uint(As[SIDX(r + 8, k0 + qc + 4)]);
        }

        unsigned bf[8][2];
        #pragma unroll
        for (int tn = 0; tn < 8; ++tn) {
            const int c = warp_n + pq + (tn >> 1) * 16 + (tn & 1) * 2;
            bf[tn][0] = __float_as_uint(Bs[SIDX(c, k0 + qc    )]);
            bf[tn][1] = __float_as_uint(Bs[SIDX(c, k0 + qc + 4)]);
        }

        #pragma unroll
        for (int tm = 0; tm < 2; ++tm)
            #pragma unroll
            for (int tn = 0; tn < 8; ++tn)
                mma_tf32(acc[tm][tn], af[tm], bf[tn]);
    }

    // ---- epilogue: thread owns cols warp_n + qc*4 + i*16 + {0..3} ----
    #pragma unroll
    for (int tm = 0; tm < 2; ++tm) {
        const int r_lo = warp_m + tm * 16 + qr;
        const float x2_lo = x2s[r_lo];
        const float x2_hi = x2s[r_lo + 8];
        const size_t off_lo = (size_t)(m_base + r_lo) * N;
        const size_t off_hi = off_lo + (size_t)8 * N;

        #pragma unroll
        for (int i = 0; i < 4; ++i) {
            const int c  = warp_n + qc * 4 + i * 16;   // local col, mult of 4
            const int gn = n_base + c;
            if (gn < N) {                              // N%4==0 -> gn+3 valid
                const float4 w2v = *(const float4*)&w2s[c];
                const float* a0 = acc[tm][2 * i];      // cols c, c+1
                const float* a1 = acc[tm][2 * i + 1];  // cols c+2, c+3

                float4 lo, hi;
                lo.x = fsqrt_approx(fmaxf(fmaf(-2.f, a0[0], x2_lo + w2v.x), 0.f));
                lo.y = fsqrt_approx(fmaxf(fmaf(-2.f, a0[1], x2_lo + w2v.y), 0.f));
                lo.z = fsqrt_approx(fmaxf(fmaf(-2.f, a1[0], x2_lo + w2v.z), 0.f));
                lo.w = fsqrt_approx(fmaxf(fmaf(-2.f, a1[1], x2_lo + w2v.w), 0.f));
                hi.x = fsqrt_approx(fmaxf(fmaf(-2.f, a0[2], x2_hi + w2v.x), 0.f));
                hi.y = fsqrt_approx(fmaxf(fmaf(-2.f, a0[3], x2_hi + w2v.y), 0.f));
                hi.z = fsqrt_approx(fmaxf(fmaf(-2.f, a1[2], x2_hi + w2v.z), 0.f));
                hi.w = fsqrt_approx(fmaxf(fmaf(-2.f, a1[3], x2_hi + w2v.w), 0.f));

                __stcs((float4*)(out + off_lo + gn), lo);
                __stcs((float4*)(out + off_hi + gn), hi);
            }
        }
    }
}

extern "C" void kernel_launch(void* const* d_in, const int* in_sizes, int n_in,
                              void* d_out, int out_size) {
    const float* x = (const float*)d_in[0];
    const float* w = (const float*)d_in[1];
    float* out     = (float*)d_out;

    int B = in_sizes[0] / KD;   // 65536
    int N = in_sizes[1] / KD;   // 4900

    dim3 grid((N + BN - 1) / BN, (B + BM - 1) / BM);
    som_mma_kernel<<<grid, 256>>>(x, w, out, B, N);
}